// round 9
// baseline (speedup 1.0000x reference)
#include <cuda_runtime.h>
#include <cuda_fp16.h>
#include <cstdint>

#define BB 256
#define TT 2048

// ---------- scratch ----------
__device__ __half g_out1h[(size_t)BB * TT * 128];     // layer-1 output fp16 [B,T,128] (fwd|bwd)
__device__ float  g_pre2p[(size_t)BB * TT * 256];     // l2 input preact, permuted [s][t][j*4+gate], bias folded (i,f,o pre-halved)
__device__ __half g_B1[2][256 * 144];                 // l1 fused B [n][k], gate-permuted n, i/f/o rows halved
__device__ __half g_B2s[256 * 128];                   // l2 scan B: [Whh2_hi|Whh2_lo], i/f/o halved
__device__ __half g_B2i[256 * 128];                   // pre2 GEMM B: Wih2 fp16, col n2=j*4+gate, i/f/o halved

// ---------- helpers ----------
__device__ __forceinline__ float tanh_f(float x) {
    float y; asm("tanh.approx.f32 %0, %1;" : "=f"(y) : "f"(x)); return y;
}
// x is PRE-HALVED preactivation
__device__ __forceinline__ float sig_h(float x) {
    return fmaf(tanh_f(x), 0.5f, 0.5f);
}
__device__ __forceinline__ __half hi_h(float v) { return __float2half_rn(v); }
__device__ __forceinline__ __half lo_h(float v) {
    return __float2half_rn(v - __half2float(__float2half_rn(v)));
}
__device__ __forceinline__ uint32_t smem_u32(const void* p) {
    uint32_t a;
    asm("{ .reg .u64 t; cvta.to.shared.u64 t, %1; cvt.u32.u64 %0, t; }" : "=r"(a) : "l"(p));
    return a;
}
__device__ __forceinline__ void ldsm4(uint32_t* r, uint32_t addr) {
    asm volatile("ldmatrix.sync.aligned.m8n8.x4.shared.b16 {%0,%1,%2,%3}, [%4];"
                 : "=r"(r[0]), "=r"(r[1]), "=r"(r[2]), "=r"(r[3]) : "r"(addr));
}
__device__ __forceinline__ void mma16816(float* d, const uint32_t* a, const uint32_t* b) {
    asm volatile("mma.sync.aligned.m16n8k16.row.col.f32.f16.f16.f32 "
                 "{%0,%1,%2,%3},{%4,%5,%6,%7},{%8,%9},{%0,%1,%2,%3};"
                 : "+f"(d[0]), "+f"(d[1]), "+f"(d[2]), "+f"(d[3])
                 : "r"(a[0]), "r"(a[1]), "r"(a[2]), "r"(a[3]), "r"(b[0]), "r"(b[1]));
}

// gate-permuted column map (ADJACENT-j version):
// tile = n>>3, c = n&7; w = tile>>2, u = (tile>>1)&1, odd = tile&1
// j = w*8 + 2*(c>>1) + u ; gate = 2*odd + (c&1) ; row = gate*64 + j
__device__ __forceinline__ int perm_row(int n) {
    int tile = n >> 3, c = n & 7;
    int w = tile >> 2, u = (tile >> 1) & 1, odd = tile & 1;
    int j = w * 8 + 2 * (c >> 1) + u;
    int gate = 2 * odd + (c & 1);
    return gate * 64 + j;
}

// =====================================================================
// Build fused B matrices (sigmoid-gate rows pre-halved).
// =====================================================================
__global__ void build_B(const float* __restrict__ Wih_f, const float* __restrict__ Whh_f,
                        const float* __restrict__ Wih_b, const float* __restrict__ Whh_b,
                        const float* __restrict__ Wih2,  const float* __restrict__ Whh2)
{
    const int n = blockIdx.x;
    const int k = threadIdx.x;
    const int r = perm_row(n);
    const float s = ((r >> 6) == 2) ? 1.f : 0.5f;   // g gate unscaled

    if (k < 144) {
        __half vf, vb;
        if      (k < 64)  { vf = hi_h(s * Whh_f[r * 64 + k]);        vb = hi_h(s * Whh_b[r * 64 + k]); }
        else if (k < 128) { vf = lo_h(s * Whh_f[r * 64 + (k - 64)]); vb = lo_h(s * Whh_b[r * 64 + (k - 64)]); }
        else if (k < 132) { vf = hi_h(s * Wih_f[r * 4 + (k - 128)]); vb = hi_h(s * Wih_b[r * 4 + (k - 128)]); }
        else if (k < 136) { vf = lo_h(s * Wih_f[r * 4 + (k - 132)]); vb = lo_h(s * Wih_b[r * 4 + (k - 132)]); }
        else              { vf = __ushort_as_half(0);                vb = __ushort_as_half(0); }
        g_B1[0][n * 144 + k] = vf;
        g_B1[1][n * 144 + k] = vb;
    }
    if (k < 128) {
        __half v = (k < 64) ? hi_h(s * Whh2[r * 64 + k]) : lo_h(s * Whh2[r * 64 + (k - 64)]);
        g_B2s[n * 128 + k] = v;
        // input-GEMM B: col n2 = j*4+gate -> weight row r2 = gate*64 + j
        const int g2 = n & 3;
        const int r2 = g2 * 64 + (n >> 2);
        const float s2 = (g2 == 2) ? 1.f : 0.5f;
        g_B2i[n * 128 + k] = __float2half_rn(s2 * Wih2[r2 * 128 + k]);
    }
}

// =====================================================================
// Layer-1 scan: 8 samples/block, one direction. 64 blocks, 256 threads.
// =====================================================================
#define AS1 152
__global__ __launch_bounds__(256, 1)
void l1_scan(const float* __restrict__ x,
             const float* __restrict__ b_f, const float* __restrict__ b_b)
{
    const int grp = blockIdx.x >> 1;
    const int dir = blockIdx.x & 1;
    const int s0  = grp * 8;
    const int tid = threadIdx.x, lane = tid & 31, w = tid >> 5;

    __shared__ __half A[2 * 16 * AS1];

    for (int i = tid; i < 2 * 16 * AS1; i += 256) A[i] = __ushort_as_half(0);

    uint32_t bf[4][9][2];
    {
        const __half* B = g_B1[dir];
#pragma unroll
        for (int tt = 0; tt < 4; tt++) {
            const int n = (w * 4 + tt) * 8 + (lane >> 2);
#pragma unroll
            for (int kt = 0; kt < 9; kt++) {
                const __half* p = B + (size_t)n * 144 + kt * 16 + 2 * (lane & 3);
                bf[tt][kt][0] = *(const uint32_t*)p;
                bf[tt][kt][1] = *(const uint32_t*)(p + 8);
            }
        }
    }

    const float* bv = dir ? b_b : b_f;
    const int p  = lane & 3;
    const int j0 = w * 8 + 2 * p, j1 = j0 + 1;
    const float bi0 = 0.5f * bv[j0], bff0 = 0.5f * bv[64 + j0], bg0 = bv[128 + j0], bo0 = 0.5f * bv[192 + j0];
    const float bi1 = 0.5f * bv[j1], bff1 = 0.5f * bv[64 + j1], bg1 = bv[128 + j1], bo1 = 0.5f * bv[192 + j1];

    const uint32_t lrow = lane & 15, lcol = (lane >> 4) * 8;
    const uint32_t aaddr0 = smem_u32(A) + (lrow * AS1 + lcol) * 2;
    const uint32_t aaddr1 = aaddr0 + 16 * AS1 * 2;

    const int step = dir ? -1 : 1;
    const int t0   = dir ? TT - 1 : 0;

    // x feeder: threads 0..31 (sample fsx, component comp)
    const bool xf = tid < 32;
    const int fsx = tid >> 2, comp = tid & 3;
    const float* xp = x + ((size_t)(s0 + fsx) * TT + t0) * 4 + comp;
    float vn = 0.f, vi = 0.f;
    if (xf) {
        float v0 = __ldg(xp);
        A[fsx * AS1 + 128 + comp] = hi_h(v0);
        A[fsx * AS1 + 132 + comp] = lo_h(v0);
        vn = __ldg(xp + step * 4);
        vi = __ldg(xp + 2 * step * 4);
    }
    __syncthreads();

    const int ffs = tid >> 4, ffc = tid & 15;
    __half* fout = g_out1h + (size_t)(s0 + ffs) * TT * 128 + dir * 64 + ffc * 4;

    const int srow = lane >> 2;
    float c0 = 0.f, c1 = 0.f;

    for (int t = 0; t < TT; t++) {
        const int cur = t & 1, nxt = cur ^ 1;
        const uint32_t aaddr = cur ? aaddr1 : aaddr0;
        __half* An = A + nxt * 16 * AS1;

        // 2-way split k accumulation (kt 0-4 / 5-8)
        float accA[4][4], accB[4][4];
#pragma unroll
        for (int i = 0; i < 4; i++)
#pragma unroll
            for (int q = 0; q < 4; q++) { accA[i][q] = 0.f; accB[i][q] = 0.f; }
#pragma unroll
        for (int kt = 0; kt < 9; kt++) {
            uint32_t a[4];
            ldsm4(a, aaddr + kt * 32);
            float (*acc)[4] = (kt < 5) ? accA : accB;
            mma16816(acc[0], a, bf[0][kt]);
            mma16816(acc[1], a, bf[1][kt]);
            mma16816(acc[2], a, bf[2][kt]);
            mma16816(acc[3], a, bf[3][kt]);
        }

        if (t && tid < 128) {
            const __half* Ac = A + cur * 16 * AS1;
            uint2 v = *(const uint2*)(Ac + ffs * AS1 + ffc * 4);
            *(uint2*)(fout + (size_t)(t0 + (t - 1) * step) * 128) = v;
        }

        if (xf) {
            An[fsx * AS1 + 128 + comp] = hi_h(vn);
            An[fsx * AS1 + 132 + comp] = lo_h(vn);
            vn = vi;
            vi = (t + 3 < TT) ? __ldg(xp + (size_t)(t + 3) * step * 4) : 0.f;
        }

        // epilogue: items j0 (accs [0],[1]) and j1 (accs [2],[3])
        {
            float iv = sig_h (accA[0][0] + accB[0][0] + bi0);
            float fv = sig_h (accA[0][1] + accB[0][1] + bff0);
            float gv = tanh_f(accA[1][0] + accB[1][0] + bg0);
            float ov = sig_h (accA[1][1] + accB[1][1] + bo0);
            c0 = fv * c0 + iv * gv;
            float h0 = ov * tanh_f(c0);

            iv = sig_h (accA[2][0] + accB[2][0] + bi1);
            fv = sig_h (accA[2][1] + accB[2][1] + bff1);
            gv = tanh_f(accA[3][0] + accB[3][0] + bg1);
            ov = sig_h (accA[3][1] + accB[3][1] + bo1);
            c1 = fv * c1 + iv * gv;
            float h1 = ov * tanh_f(c1);

            __half2 hhi = __floats2half2_rn(h0, h1);
            *(__half2*)&An[srow * AS1 + j0] = hhi;
            float2 hf = __half22float2(hhi);
            __half2 hlo = __floats2half2_rn(h0 - hf.x, h1 - hf.y);
            *(__half2*)&An[srow * AS1 + 64 + j0] = hlo;
        }
        __syncthreads();
    }

    if (tid < 128) {
        uint2 v = *(const uint2*)(A + ffs * AS1 + ffc * 4);
        *(uint2*)(fout + (size_t)(t0 + (TT - 1) * step) * 128) = v;
    }
}

// =====================================================================
// pre2 GEMM: g_pre2p[m, n2] = sum_k out1h[m,k] * B2i[n2,k] + bias (scaled)
// =====================================================================
#define ASG 136
__global__ __launch_bounds__(256, 2)
void pre2_gemm(const float* __restrict__ b2)
{
    const int m0 = blockIdx.x * 128;
    const int tid = threadIdx.x, lane = tid & 31, w = tid >> 5;

    __shared__ __half As[128 * ASG];

    {
        const uint4* src = (const uint4*)(g_out1h + (size_t)m0 * 128);
        for (int i = tid; i < 128 * 16; i += 256) {
            int rr = i >> 4, cc = i & 15;
            *(uint4*)&As[rr * ASG + cc * 8] = __ldg(src + i);
        }
    }
    __syncthreads();

    const uint32_t aaddr = smem_u32(As) + (((w * 16) + (lane & 15)) * ASG + (lane >> 4) * 8) * 2;

    float* outp = g_pre2p + (size_t)(m0 + w * 16) * 256;
    const int row0 = lane >> 2;

#pragma unroll 1
    for (int ng = 0; ng < 8; ng++) {
        uint32_t bfr[4][8][2];
#pragma unroll
        for (int tt = 0; tt < 4; tt++) {
            const int n = ng * 32 + tt * 8 + (lane >> 2);
#pragma unroll
            for (int kt = 0; kt < 8; kt++) {
                const __half* p = g_B2i + (size_t)n * 128 + kt * 16 + 2 * (lane & 3);
                bfr[tt][kt][0] = *(const uint32_t*)p;
                bfr[tt][kt][1] = *(const uint32_t*)(p + 8);
            }
        }

        float acc[4][4];
#pragma unroll
        for (int i = 0; i < 4; i++) { acc[i][0] = 0.f; acc[i][1] = 0.f; acc[i][2] = 0.f; acc[i][3] = 0.f; }
#pragma unroll
        for (int kt = 0; kt < 8; kt++) {
            uint32_t a[4];
            ldsm4(a, aaddr + kt * 32);
            mma16816(acc[0], a, bfr[0][kt]);
            mma16816(acc[1], a, bfr[1][kt]);
            mma16816(acc[2], a, bfr[2][kt]);
            mma16816(acc[3], a, bfr[3][kt]);
        }

#pragma unroll
        for (int tt = 0; tt < 4; tt++) {
            const int col = ng * 32 + tt * 8 + 2 * (lane & 3);
            const int ra = (col & 3) * 64 + (col >> 2);
            const int rb = ((col + 1) & 3) * 64 + ((col + 1) >> 2);
            const float sa = ((col & 3) == 2) ? 1.f : 0.5f;   // gate g unscaled
            const float ba = __ldg(b2 + ra) * sa;
            const float bb = __ldg(b2 + rb) * 0.5f;           // gates f/o always sigmoid
            float2 v0 = make_float2(acc[tt][0] + ba, acc[tt][1] + bb);
            float2 v1 = make_float2(acc[tt][2] + ba, acc[tt][3] + bb);
            *(float2*)(outp + (size_t)row0 * 256 + col)       = v0;
            *(float2*)(outp + (size_t)(row0 + 8) * 256 + col) = v1;
        }
    }
}

// =====================================================================
// Layer-2 scan: 8 samples/block, 32 blocks. K=128 (h hi/lo).
// =====================================================================
#define AS2 136
__global__ __launch_bounds__(256, 1)
void l2_scan(const float* __restrict__ Wfc, const float* __restrict__ bfc,
             float* __restrict__ out)
{
    const int s0  = blockIdx.x * 8;
    const int tid = threadIdx.x, lane = tid & 31, w = tid >> 5;

    __shared__ __half A[2 * 16 * AS2];
    __shared__ float  sred[8 * 64];

    for (int i = tid; i < 2 * 16 * AS2; i += 256) A[i] = __ushort_as_half(0);

    uint32_t bf[4][8][2];
#pragma unroll
    for (int tt = 0; tt < 4; tt++) {
        const int n = (w * 4 + tt) * 8 + (lane >> 2);
#pragma unroll
        for (int kt = 0; kt < 8; kt++) {
            const __half* p = g_B2s + (size_t)n * 128 + kt * 16 + 2 * (lane & 3);
            bf[tt][kt][0] = *(const uint32_t*)p;
            bf[tt][kt][1] = *(const uint32_t*)(p + 8);
        }
    }

    const int p  = lane & 3;
    const int j0 = w * 8 + 2 * p, j1 = j0 + 1;
    const float wf0 = __ldg(Wfc + j0), wf1 = __ldg(Wfc + j1);

    const uint32_t lrow = lane & 15, lcol = (lane >> 4) * 8;
    const uint32_t aaddr0 = smem_u32(A) + (lrow * AS2 + lcol) * 2;
    const uint32_t aaddr1 = aaddr0 + 16 * AS2 * 2;

    const int srow = lane >> 2;

    // pre2 stream: quads for items j0, j1 are contiguous 32B
    const float* pp = g_pre2p + (size_t)(s0 + srow) * TT * 256 + j0 * 4;
    float4 pc0 = *(const float4*)(pp);
    float4 pc1 = *(const float4*)(pp + 4);
    float4 pn0 = *(const float4*)(pp + 256);
    float4 pn1 = *(const float4*)(pp + 260);
    __syncthreads();

    float c0 = 0.f, c1 = 0.f;
    float h0 = 0.f, h1 = 0.f;

    for (int t = 0; t < TT; t++) {
        const int cur = t & 1, nxt = cur ^ 1;
        const uint32_t aaddr = cur ? aaddr1 : aaddr0;
        __half* An = A + nxt * 16 * AS2;

        float accA[4][4], accB[4][4];
#pragma unroll
        for (int i = 0; i < 4; i++)
#pragma unroll
            for (int q = 0; q < 4; q++) { accA[i][q] = 0.f; accB[i][q] = 0.f; }
#pragma unroll
        for (int kt = 0; kt < 8; kt++) {
            uint32_t a[4];
            ldsm4(a, aaddr + kt * 32);
            float (*acc)[4] = (kt < 4) ? accA : accB;
            mma16816(acc[0], a, bf[0][kt]);
            mma16816(acc[1], a, bf[1][kt]);
            mma16816(acc[2], a, bf[2][kt]);
            mma16816(acc[3], a, bf[3][kt]);
        }

        float4 pf0, pf1;
        if (t + 2 < TT) {
            pf0 = *(const float4*)(pp + (size_t)(t + 2) * 256);
            pf1 = *(const float4*)(pp + (size_t)(t + 2) * 256 + 4);
        } else { pf0 = make_float4(0.f,0.f,0.f,0.f); pf1 = pf0; }

        {
            float iv = sig_h (accA[0][0] + accB[0][0] + pc0.x);
            float fv = sig_h (accA[0][1] + accB[0][1] + pc0.y);
            float gv = tanh_f(accA[1][0] + accB[1][0] + pc0.z);
            float ov = sig_h (accA[1][1] + accB[1][1] + pc0.w);
            c0 = fv * c0 + iv * gv;
            h0 = ov * tanh_f(c0);

            iv = sig_h (accA[2][0] + accB[2][0] + pc1.x);
            fv = sig_h (accA[2][1] + accB[2][1] + pc1.y);
            gv = tanh_f(accA[3][0] + accB[3][0] + pc1.z);
            ov = sig_h (accA[3][1] + accB[3][1] + pc1.w);
            c1 = fv * c1 + iv * gv;
            h1 = ov * tanh_f(c1);

            __half2 hhi = __floats2half2_rn(h0, h1);
            *(__half2*)&An[srow * AS2 + j0] = hhi;
            float2 hf = __half22float2(hhi);
            __half2 hlo = __floats2half2_rn(h0 - hf.x, h1 - hf.y);
            *(__half2*)&An[srow * AS2 + 64 + j0] = hlo;
        }

        pc0 = pn0; pc1 = pn1; pn0 = pf0; pn1 = pf1;
        __syncthreads();
    }

    sred[srow * 64 + j0] = h0 * wf0;
    sred[srow * 64 + j1] = h1 * wf1;
    __syncthreads();
    if (tid < 8) {
        float acc = __ldg(bfc);
#pragma unroll
        for (int k = 0; k < 64; k++) acc += sred[tid * 64 + k];
        out[s0 + tid] = acc;
    }
}

// =====================================================================
extern "C" void kernel_launch(void* const* d_in, const int* in_sizes, int n_in,
                              void* d_out, int out_size)
{
    const float* x     = (const float*)d_in[0];
    const float* Wih_f = (const float*)d_in[1];
    const float* Whh_f = (const float*)d_in[2];
    const float* b_f   = (const float*)d_in[3];
    const float* Wih_b = (const float*)d_in[4];
    const float* Whh_b = (const float*)d_in[5];
    const float* b_b   = (const float*)d_in[6];
    const float* Wih2  = (const float*)d_in[7];
    const float* Whh2  = (const float*)d_in[8];
    const float* b2    = (const float*)d_in[9];
    const float* Wfc   = (const float*)d_in[10];
    const float* bfc   = (const float*)d_in[11];
    float* out = (float*)d_out;

    build_B<<<256, 256>>>(Wih_f, Whh_f, Wih_b, Whh_b, Wih2, Whh2);
    l1_scan<<<64, 256>>>(x, b_f, b_b);
    pre2_gemm<<<(BB * TT) / 128, 256>>>(b2);
    l2_scan<<<32, 256>>>(Wfc, bfc, out);
}

// round 10
// speedup vs baseline: 1.1632x; 1.1632x over previous
#include <cuda_runtime.h>
#include <cuda_fp16.h>
#include <cstdint>

#define BB 256
#define TT 2048

// ---------- scratch ----------
__device__ __half g_out1h[(size_t)BB * TT * 128];     // layer-1 output fp16 [B,T,128] (fwd|bwd)
__device__ float  g_pre2p[(size_t)BB * TT * 256];     // l2 input preact, permuted, bias folded (i,f,o pre-halved)
__device__ __half g_B1[2][256 * 80];                  // l1 fused B [n][k]: [Whh_hi(64)|Wih_hi(4)|Wih_hi(4)|0(8)]
__device__ __half g_B2s[256 * 64];                    // l2 scan B: Whh2_hi, i/f/o halved
__device__ __half g_B2i[256 * 128];                   // pre2 GEMM B: Wih2 fp16, col n2=j*4+gate, i/f/o halved

// ---------- helpers ----------
__device__ __forceinline__ float tanh_f(float x) {
    float y; asm("tanh.approx.f32 %0, %1;" : "=f"(y) : "f"(x)); return y;
}
// x is PRE-HALVED preactivation
__device__ __forceinline__ float sig_h(float x) {
    return fmaf(tanh_f(x), 0.5f, 0.5f);
}
__device__ __forceinline__ __half hi_h(float v) { return __float2half_rn(v); }
__device__ __forceinline__ __half lo_h(float v) {
    return __float2half_rn(v - __half2float(__float2half_rn(v)));
}
__device__ __forceinline__ uint32_t smem_u32(const void* p) {
    uint32_t a;
    asm("{ .reg .u64 t; cvta.to.shared.u64 t, %1; cvt.u32.u64 %0, t; }" : "=r"(a) : "l"(p));
    return a;
}
__device__ __forceinline__ void ldsm4(uint32_t* r, uint32_t addr) {
    asm volatile("ldmatrix.sync.aligned.m8n8.x4.shared.b16 {%0,%1,%2,%3}, [%4];"
                 : "=r"(r[0]), "=r"(r[1]), "=r"(r[2]), "=r"(r[3]) : "r"(addr));
}
__device__ __forceinline__ void mma16816(float* d, const uint32_t* a, const uint32_t* b) {
    asm volatile("mma.sync.aligned.m16n8k16.row.col.f32.f16.f16.f32 "
                 "{%0,%1,%2,%3},{%4,%5,%6,%7},{%8,%9},{%0,%1,%2,%3};"
                 : "+f"(d[0]), "+f"(d[1]), "+f"(d[2]), "+f"(d[3])
                 : "r"(a[0]), "r"(a[1]), "r"(a[2]), "r"(a[3]), "r"(b[0]), "r"(b[1]));
}

// gate-permuted column map (adjacent-j):
// tile = n>>3, c = n&7; w = tile>>2, u = (tile>>1)&1, odd = tile&1
// j = w*8 + 2*(c>>1) + u ; gate = 2*odd + (c&1) ; row = gate*64 + j
__device__ __forceinline__ int perm_row(int n) {
    int tile = n >> 3, c = n & 7;
    int w = tile >> 2, u = (tile >> 1) & 1, odd = tile & 1;
    int j = w * 8 + 2 * (c >> 1) + u;
    int gate = 2 * odd + (c & 1);
    return gate * 64 + j;
}

// =====================================================================
// Build fused B matrices (sigmoid-gate rows pre-halved).
// =====================================================================
__global__ void build_B(const float* __restrict__ Wih_f, const float* __restrict__ Whh_f,
                        const float* __restrict__ Wih_b, const float* __restrict__ Whh_b,
                        const float* __restrict__ Wih2,  const float* __restrict__ Whh2)
{
    const int n = blockIdx.x;
    const int k = threadIdx.x;
    const int r = perm_row(n);
    const float s = ((r >> 6) == 2) ? 1.f : 0.5f;   // g gate unscaled

    if (k < 80) {
        __half vf, vb;
        if      (k < 64) { vf = hi_h(s * Whh_f[r * 64 + k]);        vb = hi_h(s * Whh_b[r * 64 + k]); }
        else if (k < 68) { vf = hi_h(s * Wih_f[r * 4 + (k - 64)]);  vb = hi_h(s * Wih_b[r * 4 + (k - 64)]); }
        else if (k < 72) { vf = hi_h(s * Wih_f[r * 4 + (k - 68)]);  vb = hi_h(s * Wih_b[r * 4 + (k - 68)]); }
        else             { vf = __ushort_as_half(0);                vb = __ushort_as_half(0); }
        g_B1[0][n * 80 + k] = vf;
        g_B1[1][n * 80 + k] = vb;
    }
    if (k < 64) {
        g_B2s[n * 64 + k] = hi_h(s * Whh2[r * 64 + k]);
    }
    if (k < 128) {
        // input-GEMM B: col n2 = j*4+gate -> weight row r2 = gate*64 + j
        const int g2 = n & 3;
        const int r2 = g2 * 64 + (n >> 2);
        const float s2 = (g2 == 2) ? 1.f : 0.5f;
        g_B2i[n * 128 + k] = __float2half_rn(s2 * Wih2[r2 * 128 + k]);
    }
}

// =====================================================================
// Layer-1 scan: 8 samples/block, one direction. 64 blocks, 256 threads.
// A[16 x 80] fp16 (stride 88): [h_hi(64) | x_hi(4) | x_lo(4) | pad]. 5 kt.
// =====================================================================
#define AS1 88
__global__ __launch_bounds__(256, 1)
void l1_scan(const float* __restrict__ x,
             const float* __restrict__ b_f, const float* __restrict__ b_b)
{
    const int grp = blockIdx.x >> 1;
    const int dir = blockIdx.x & 1;
    const int s0  = grp * 8;
    const int tid = threadIdx.x, lane = tid & 31, w = tid >> 5;

    __shared__ __half A[2 * 16 * AS1];

    for (int i = tid; i < 2 * 16 * AS1; i += 256) A[i] = __ushort_as_half(0);

    uint32_t bf[4][5][2];
    {
        const __half* B = g_B1[dir];
#pragma unroll
        for (int tt = 0; tt < 4; tt++) {
            const int n = (w * 4 + tt) * 8 + (lane >> 2);
#pragma unroll
            for (int kt = 0; kt < 5; kt++) {
                const __half* p = B + (size_t)n * 80 + kt * 16 + 2 * (lane & 3);
                bf[tt][kt][0] = *(const uint32_t*)p;
                bf[tt][kt][1] = *(const uint32_t*)(p + 8);
            }
        }
    }

    const float* bv = dir ? b_b : b_f;
    const int p  = lane & 3;
    const int j0 = w * 8 + 2 * p, j1 = j0 + 1;
    const float bi0 = 0.5f * bv[j0], bff0 = 0.5f * bv[64 + j0], bg0 = bv[128 + j0], bo0 = 0.5f * bv[192 + j0];
    const float bi1 = 0.5f * bv[j1], bff1 = 0.5f * bv[64 + j1], bg1 = bv[128 + j1], bo1 = 0.5f * bv[192 + j1];

    const uint32_t lrow = lane & 15, lcol = (lane >> 4) * 8;
    const uint32_t aaddr0 = smem_u32(A) + (lrow * AS1 + lcol) * 2;
    const uint32_t aaddr1 = aaddr0 + 16 * AS1 * 2;

    const int step = dir ? -1 : 1;
    const int t0   = dir ? TT - 1 : 0;

    // x feeder: threads 0..31 (sample fsx, component comp)
    const bool xf = tid < 32;
    const int fsx = tid >> 2, comp = tid & 3;
    const float* xp = x + ((size_t)(s0 + fsx) * TT + t0) * 4 + comp;
    float vn = 0.f, vi = 0.f;
    if (xf) {
        float v0 = __ldg(xp);
        A[fsx * AS1 + 64 + comp] = hi_h(v0);
        A[fsx * AS1 + 68 + comp] = lo_h(v0);
        vn = __ldg(xp + step * 4);
        vi = __ldg(xp + 2 * step * 4);
    }
    __syncthreads();

    const int ffs = tid >> 4, ffc = tid & 15;
    __half* fout = g_out1h + (size_t)(s0 + ffs) * TT * 128 + dir * 64 + ffc * 4;

    const int srow = lane >> 2;
    float c0 = 0.f, c1 = 0.f;

    for (int t = 0; t < TT; t++) {
        const int cur = t & 1, nxt = cur ^ 1;
        const uint32_t aaddr = cur ? aaddr1 : aaddr0;
        __half* An = A + nxt * 16 * AS1;

        // 2-way split k accumulation (kt 0-2 / 3-4)
        float accA[4][4], accB[4][4];
#pragma unroll
        for (int i = 0; i < 4; i++)
#pragma unroll
            for (int q = 0; q < 4; q++) { accA[i][q] = 0.f; accB[i][q] = 0.f; }
#pragma unroll
        for (int kt = 0; kt < 5; kt++) {
            uint32_t a[4];
            ldsm4(a, aaddr + kt * 32);
            float (*acc)[4] = (kt < 3) ? accA : accB;
            mma16816(acc[0], a, bf[0][kt]);
            mma16816(acc[1], a, bf[1][kt]);
            mma16816(acc[2], a, bf[2][kt]);
            mma16816(acc[3], a, bf[3][kt]);
        }

        if (t && tid < 128) {
            const __half* Ac = A + cur * 16 * AS1;
            uint2 v = *(const uint2*)(Ac + ffs * AS1 + ffc * 4);
            *(uint2*)(fout + (size_t)(t0 + (t - 1) * step) * 128) = v;
        }

        if (xf) {
            An[fsx * AS1 + 64 + comp] = hi_h(vn);
            An[fsx * AS1 + 68 + comp] = lo_h(vn);
            vn = vi;
            vi = (t + 3 < TT) ? __ldg(xp + (size_t)(t + 3) * step * 4) : 0.f;
        }

        // epilogue: items j0 (accs [0],[1]) and j1 (accs [2],[3])
        {
            float iv = sig_h (accA[0][0] + accB[0][0] + bi0);
            float fv = sig_h (accA[0][1] + accB[0][1] + bff0);
            float gv = tanh_f(accA[1][0] + accB[1][0] + bg0);
            float ov = sig_h (accA[1][1] + accB[1][1] + bo0);
            c0 = fv * c0 + iv * gv;
            float h0 = ov * tanh_f(c0);

            iv = sig_h (accA[2][0] + accB[2][0] + bi1);
            fv = sig_h (accA[2][1] + accB[2][1] + bff1);
            gv = tanh_f(accA[3][0] + accB[3][0] + bg1);
            ov = sig_h (accA[3][1] + accB[3][1] + bo1);
            c1 = fv * c1 + iv * gv;
            float h1 = ov * tanh_f(c1);

            __half2 hhi = __floats2half2_rn(h0, h1);
            *(__half2*)&An[srow * AS1 + j0] = hhi;
        }
        __syncthreads();
    }

    if (tid < 128) {
        uint2 v = *(const uint2*)(A + ffs * AS1 + ffc * 4);
        *(uint2*)(fout + (size_t)(t0 + (TT - 1) * step) * 128) = v;
    }
}

// =====================================================================
// pre2 GEMM: g_pre2p[m, n2] = sum_k out1h[m,k] * B2i[n2,k] + bias (scaled)
// =====================================================================
#define ASG 136
__global__ __launch_bounds__(256, 2)
void pre2_gemm(const float* __restrict__ b2)
{
    const int m0 = blockIdx.x * 128;
    const int tid = threadIdx.x, lane = tid & 31, w = tid >> 5;

    __shared__ __half As[128 * ASG];

    {
        const uint4* src = (const uint4*)(g_out1h + (size_t)m0 * 128);
        for (int i = tid; i < 128 * 16; i += 256) {
            int rr = i >> 4, cc = i & 15;
            *(uint4*)&As[rr * ASG + cc * 8] = __ldg(src + i);
        }
    }
    __syncthreads();

    const uint32_t aaddr = smem_u32(As) + (((w * 16) + (lane & 15)) * ASG + (lane >> 4) * 8) * 2;

    float* outp = g_pre2p + (size_t)(m0 + w * 16) * 256;
    const int row0 = lane >> 2;

#pragma unroll 1
    for (int ng = 0; ng < 8; ng++) {
        uint32_t bfr[4][8][2];
#pragma unroll
        for (int tt = 0; tt < 4; tt++) {
            const int n = ng * 32 + tt * 8 + (lane >> 2);
#pragma unroll
            for (int kt = 0; kt < 8; kt++) {
                const __half* p = g_B2i + (size_t)n * 128 + kt * 16 + 2 * (lane & 3);
                bfr[tt][kt][0] = *(const uint32_t*)p;
                bfr[tt][kt][1] = *(const uint32_t*)(p + 8);
            }
        }

        float acc[4][4];
#pragma unroll
        for (int i = 0; i < 4; i++) { acc[i][0] = 0.f; acc[i][1] = 0.f; acc[i][2] = 0.f; acc[i][3] = 0.f; }
#pragma unroll
        for (int kt = 0; kt < 8; kt++) {
            uint32_t a[4];
            ldsm4(a, aaddr + kt * 32);
            mma16816(acc[0], a, bfr[0][kt]);
            mma16816(acc[1], a, bfr[1][kt]);
            mma16816(acc[2], a, bfr[2][kt]);
            mma16816(acc[3], a, bfr[3][kt]);
        }

#pragma unroll
        for (int tt = 0; tt < 4; tt++) {
            const int col = ng * 32 + tt * 8 + 2 * (lane & 3);
            const int ra = (col & 3) * 64 + (col >> 2);
            const int rb = ((col + 1) & 3) * 64 + ((col + 1) >> 2);
            const float sa = ((col & 3) == 2) ? 1.f : 0.5f;   // gate g unscaled
            const float ba = __ldg(b2 + ra) * sa;
            const float bb = __ldg(b2 + rb) * 0.5f;           // gates f/o always sigmoid
            float2 v0 = make_float2(acc[tt][0] + ba, acc[tt][1] + bb);
            float2 v1 = make_float2(acc[tt][2] + ba, acc[tt][3] + bb);
            *(float2*)(outp + (size_t)row0 * 256 + col)       = v0;
            *(float2*)(outp + (size_t)(row0 + 8) * 256 + col) = v1;
        }
    }
}

// =====================================================================
// Layer-2 scan: 8 samples/block, 32 blocks. K=64 (h_hi only), 4 kt.
// =====================================================================
#define AS2 72
__global__ __launch_bounds__(256, 1)
void l2_scan(const float* __restrict__ Wfc, const float* __restrict__ bfc,
             float* __restrict__ out)
{
    const int s0  = blockIdx.x * 8;
    const int tid = threadIdx.x, lane = tid & 31, w = tid >> 5;

    __shared__ __half A[2 * 16 * AS2];
    __shared__ float  sred[8 * 64];

    for (int i = tid; i < 2 * 16 * AS2; i += 256) A[i] = __ushort_as_half(0);

    uint32_t bf[4][4][2];
#pragma unroll
    for (int tt = 0; tt < 4; tt++) {
        const int n = (w * 4 + tt) * 8 + (lane >> 2);
#pragma unroll
        for (int kt = 0; kt < 4; kt++) {
            const __half* p = g_B2s + (size_t)n * 64 + kt * 16 + 2 * (lane & 3);
            bf[tt][kt][0] = *(const uint32_t*)p;
            bf[tt][kt][1] = *(const uint32_t*)(p + 8);
        }
    }

    const int p  = lane & 3;
    const int j0 = w * 8 + 2 * p, j1 = j0 + 1;
    const float wf0 = __ldg(Wfc + j0), wf1 = __ldg(Wfc + j1);

    const uint32_t lrow = lane & 15, lcol = (lane >> 4) * 8;
    const uint32_t aaddr0 = smem_u32(A) + (lrow * AS2 + lcol) * 2;
    const uint32_t aaddr1 = aaddr0 + 16 * AS2 * 2;

    const int srow = lane >> 2;

    // pre2 stream: quads for items j0, j1 contiguous 32B
    const float* pp = g_pre2p + (size_t)(s0 + srow) * TT * 256 + j0 * 4;
    float4 pc0 = *(const float4*)(pp);
    float4 pc1 = *(const float4*)(pp + 4);
    float4 pn0 = *(const float4*)(pp + 256);
    float4 pn1 = *(const float4*)(pp + 260);
    __syncthreads();

    float c0 = 0.f, c1 = 0.f;
    float h0 = 0.f, h1 = 0.f;

    for (int t = 0; t < TT; t++) {
        const int cur = t & 1, nxt = cur ^ 1;
        const uint32_t aaddr = cur ? aaddr1 : aaddr0;
        __half* An = A + nxt * 16 * AS2;

        float accA[4][4], accB[4][4];
#pragma unroll
        for (int i = 0; i < 4; i++)
#pragma unroll
            for (int q = 0; q < 4; q++) { accA[i][q] = 0.f; accB[i][q] = 0.f; }
#pragma unroll
        for (int kt = 0; kt < 4; kt++) {
            uint32_t a[4];
            ldsm4(a, aaddr + kt * 32);
            float (*acc)[4] = (kt < 2) ? accA : accB;
            mma16816(acc[0], a, bf[0][kt]);
            mma16816(acc[1], a, bf[1][kt]);
            mma16816(acc[2], a, bf[2][kt]);
            mma16816(acc[3], a, bf[3][kt]);
        }

        float4 pf0, pf1;
        if (t + 2 < TT) {
            pf0 = *(const float4*)(pp + (size_t)(t + 2) * 256);
            pf1 = *(const float4*)(pp + (size_t)(t + 2) * 256 + 4);
        } else { pf0 = make_float4(0.f,0.f,0.f,0.f); pf1 = pf0; }

        {
            float iv = sig_h (accA[0][0] + accB[0][0] + pc0.x);
            float fv = sig_h (accA[0][1] + accB[0][1] + pc0.y);
            float gv = tanh_f(accA[1][0] + accB[1][0] + pc0.z);
            float ov = sig_h (accA[1][1] + accB[1][1] + pc0.w);
            c0 = fv * c0 + iv * gv;
            h0 = ov * tanh_f(c0);

            iv = sig_h (accA[2][0] + accB[2][0] + pc1.x);
            fv = sig_h (accA[2][1] + accB[2][1] + pc1.y);
            gv = tanh_f(accA[3][0] + accB[3][0] + pc1.z);
            ov = sig_h (accA[3][1] + accB[3][1] + pc1.w);
            c1 = fv * c1 + iv * gv;
            h1 = ov * tanh_f(c1);

            __half2 hhi = __floats2half2_rn(h0, h1);
            *(__half2*)&An[srow * AS2 + j0] = hhi;
        }

        pc0 = pn0; pc1 = pn1; pn0 = pf0; pn1 = pf1;
        __syncthreads();
    }

    sred[srow * 64 + j0] = h0 * wf0;
    sred[srow * 64 + j1] = h1 * wf1;
    __syncthreads();
    if (tid < 8) {
        float acc = __ldg(bfc);
#pragma unroll
        for (int k = 0; k < 64; k++) acc += sred[tid * 64 + k];
        out[s0 + tid] = acc;
    }
}

// =====================================================================
extern "C" void kernel_launch(void* const* d_in, const int* in_sizes, int n_in,
                              void* d_out, int out_size)
{
    const float* x     = (const float*)d_in[0];
    const float* Wih_f = (const float*)d_in[1];
    const float* Whh_f = (const float*)d_in[2];
    const float* b_f   = (const float*)d_in[3];
    const float* Wih_b = (const float*)d_in[4];
    const float* Whh_b = (const float*)d_in[5];
    const float* b_b   = (const float*)d_in[6];
    const float* Wih2  = (const float*)d_in[7];
    const float* Whh2  = (const float*)d_in[8];
    const float* b2    = (const float*)d_in[9];
    const float* Wfc   = (const float*)d_in[10];
    const float* bfc   = (const float*)d_in[11];
    float* out = (float*)d_out;

    build_B<<<256, 256>>>(Wih_f, Whh_f, Wih_b, Whh_b, Wih2, Whh2);
    l1_scan<<<64, 256>>>(x, b_f, b_b);
    pre2_gemm<<<(BB * TT) / 128, 256>>>(b2);
    l2_scan<<<32, 256>>>(Wfc, bfc, out);
}

// round 11
// speedup vs baseline: 1.1669x; 1.0031x over previous
#include <cuda_runtime.h>
#include <cuda_fp16.h>
#include <cstdint>

#define BB 256
#define TT 2048

// ---------- scratch ----------
__device__ __half g_out1h[(size_t)BB * TT * 128];     // layer-1 output fp16 [B,T,128] (fwd|bwd)
__device__ float  g_pre2p[(size_t)BB * TT * 256];     // l2 input preact, permuted, bias folded (i,f,o pre-halved)
__device__ __half g_B1[2][256 * 80];                  // l1 fused B [n][k]: [Whh_hi(64)|Wih_hi(4)|Wih_lo(4)|0(8)]
__device__ __half g_B2s[256 * 64];                    // l2 scan B: Whh2_hi, i/f/o halved
__device__ __half g_B2i[256 * 128];                   // pre2 GEMM B: Wih2 fp16, col n2=j*4+gate, i/f/o halved

// ---------- helpers ----------
__device__ __forceinline__ float tanh_f(float x) {
    float y; asm("tanh.approx.f32 %0, %1;" : "=f"(y) : "f"(x)); return y;
}
// x is PRE-HALVED preactivation
__device__ __forceinline__ float sig_h(float x) {
    return fmaf(tanh_f(x), 0.5f, 0.5f);
}
__device__ __forceinline__ __half hi_h(float v) { return __float2half_rn(v); }
__device__ __forceinline__ __half lo_h(float v) {
    return __float2half_rn(v - __half2float(__float2half_rn(v)));
}
__device__ __forceinline__ uint32_t smem_u32(const void* p) {
    uint32_t a;
    asm("{ .reg .u64 t; cvta.to.shared.u64 t, %1; cvt.u32.u64 %0, t; }" : "=r"(a) : "l"(p));
    return a;
}
__device__ __forceinline__ void ldsm4(uint32_t* r, uint32_t addr) {
    asm volatile("ldmatrix.sync.aligned.m8n8.x4.shared.b16 {%0,%1,%2,%3}, [%4];"
                 : "=r"(r[0]), "=r"(r[1]), "=r"(r[2]), "=r"(r[3]) : "r"(addr));
}
__device__ __forceinline__ void mma16816(float* d, const uint32_t* a, const uint32_t* b) {
    asm volatile("mma.sync.aligned.m16n8k16.row.col.f32.f16.f16.f32 "
                 "{%0,%1,%2,%3},{%4,%5,%6,%7},{%8,%9},{%0,%1,%2,%3};"
                 : "+f"(d[0]), "+f"(d[1]), "+f"(d[2]), "+f"(d[3])
                 : "r"(a[0]), "r"(a[1]), "r"(a[2]), "r"(a[3]), "r"(b[0]), "r"(b[1]));
}

// gate-permuted column map (adjacent-j):
// tile = n>>3, c = n&7; wq = tile>>2, u = (tile>>1)&1, odd = tile&1
// j = wq*8 + 2*(c>>1) + u ; gate = 2*odd + (c&1) ; row = gate*64 + j
__device__ __forceinline__ int perm_row(int n) {
    int tile = n >> 3, c = n & 7;
    int wq = tile >> 2, u = (tile >> 1) & 1, odd = tile & 1;
    int j = wq * 8 + 2 * (c >> 1) + u;
    int gate = 2 * odd + (c & 1);
    return gate * 64 + j;
}

// =====================================================================
// Build fused B matrices (sigmoid-gate rows pre-halved).
// =====================================================================
__global__ void build_B(const float* __restrict__ Wih_f, const float* __restrict__ Whh_f,
                        const float* __restrict__ Wih_b, const float* __restrict__ Whh_b,
                        const float* __restrict__ Wih2,  const float* __restrict__ Whh2)
{
    const int n = blockIdx.x;
    const int k = threadIdx.x;
    const int r = perm_row(n);
    const float s = ((r >> 6) == 2) ? 1.f : 0.5f;   // g gate unscaled

    if (k < 80) {
        __half vf, vb;
        if      (k < 64) { vf = hi_h(s * Whh_f[r * 64 + k]);        vb = hi_h(s * Whh_b[r * 64 + k]); }
        else if (k < 68) { vf = hi_h(s * Wih_f[r * 4 + (k - 64)]);  vb = hi_h(s * Wih_b[r * 4 + (k - 64)]); }
        else if (k < 72) { vf = hi_h(s * Wih_f[r * 4 + (k - 68)]);  vb = hi_h(s * Wih_b[r * 4 + (k - 68)]); }
        else             { vf = __ushort_as_half(0);                vb = __ushort_as_half(0); }
        g_B1[0][n * 80 + k] = vf;
        g_B1[1][n * 80 + k] = vb;
    }
    if (k < 64) {
        g_B2s[n * 64 + k] = hi_h(s * Whh2[r * 64 + k]);
    }
    if (k < 128) {
        const int g2 = n & 3;
        const int r2 = g2 * 64 + (n >> 2);
        const float s2 = (g2 == 2) ? 1.f : 0.5f;
        g_B2i[n * 128 + k] = __float2half_rn(s2 * Wih2[r2 * 128 + k]);
    }
}

// =====================================================================
// Layer-1 scan: 8 samples/block, one direction. 64 blocks, 512 threads.
// Warp w (0-15) owns n8-tiles {2w, 2w+1} -> 1 LSTM cell per lane.
// A[16 x 80] fp16 (stride 88): [h_hi(64) | x_hi(4) | x_lo(4) | pad]. 5 kt.
// =====================================================================
#define AS1 88
__global__ __launch_bounds__(512, 1)
void l1_scan(const float* __restrict__ x,
             const float* __restrict__ b_f, const float* __restrict__ b_b)
{
    const int grp = blockIdx.x >> 1;
    const int dir = blockIdx.x & 1;
    const int s0  = grp * 8;
    const int tid = threadIdx.x, lane = tid & 31, w = tid >> 5;

    __shared__ __half A[2 * 16 * AS1];

    for (int i = tid; i < 2 * 16 * AS1; i += 512) A[i] = __ushort_as_half(0);

    // B fragments: warp w owns tiles 2w (gates i,f) and 2w+1 (gates g,o)
    uint32_t bf[2][5][2];
    {
        const __half* B = g_B1[dir];
#pragma unroll
        for (int tt = 0; tt < 2; tt++) {
            const int n = (2 * w + tt) * 8 + (lane >> 2);
#pragma unroll
            for (int kt = 0; kt < 5; kt++) {
                const __half* p = B + (size_t)n * 80 + kt * 16 + 2 * (lane & 3);
                bf[tt][kt][0] = *(const uint32_t*)p;
                bf[tt][kt][1] = *(const uint32_t*)(p + 8);
            }
        }
    }

    // cell identity: one LSTM cell per lane
    const int srow = lane >> 2;                            // sample row 0..7
    const int j    = (w >> 1) * 8 + 2 * (lane & 3) + (w & 1);
    const float* bv = dir ? b_b : b_f;
    const float bi  = 0.5f * bv[j];
    const float bff = 0.5f * bv[64 + j];
    const float bg  = bv[128 + j];
    const float bo  = 0.5f * bv[192 + j];

    const uint32_t lrow = lane & 15, lcol = (lane >> 4) * 8;
    const uint32_t aaddr0 = smem_u32(A) + (lrow * AS1 + lcol) * 2;
    const uint32_t aaddr1 = aaddr0 + 16 * AS1 * 2;

    const int step = dir ? -1 : 1;
    const int t0   = dir ? TT - 1 : 0;

    // x feeder: threads 0..31 (sample fsx, component comp)
    const bool xf = tid < 32;
    const int fsx = tid >> 2, comp = tid & 3;
    const float* xp = x + ((size_t)(s0 + fsx) * TT + t0) * 4 + comp;
    float vn = 0.f, vi = 0.f;
    if (xf) {
        float v0 = __ldg(xp);
        A[fsx * AS1 + 64 + comp] = hi_h(v0);
        A[fsx * AS1 + 68 + comp] = lo_h(v0);
        vn = __ldg(xp + step * 4);
        vi = __ldg(xp + 2 * step * 4);
    }
    __syncthreads();

    const int ffs = tid >> 4, ffc = tid & 15;
    __half* fout = g_out1h + (size_t)(s0 + ffs) * TT * 128 + dir * 64 + ffc * 4;

    float c = 0.f;

    for (int t = 0; t < TT; t++) {
        const int cur = t & 1, nxt = cur ^ 1;
        const uint32_t aaddr = cur ? aaddr1 : aaddr0;
        __half* An = A + nxt * 16 * AS1;

        // 2-way split k accumulation (kt 0-2 / 3-4), tiles 0 (i,f) and 1 (g,o)
        float aA0[4], aB0[4], aA1[4], aB1[4];
#pragma unroll
        for (int q = 0; q < 4; q++) { aA0[q] = 0.f; aB0[q] = 0.f; aA1[q] = 0.f; aB1[q] = 0.f; }
#pragma unroll
        for (int kt = 0; kt < 5; kt++) {
            uint32_t a[4];
            ldsm4(a, aaddr + kt * 32);
            if (kt < 3) { mma16816(aA0, a, bf[0][kt]); mma16816(aA1, a, bf[1][kt]); }
            else        { mma16816(aB0, a, bf[0][kt]); mma16816(aB1, a, bf[1][kt]); }
        }

        // flush previous step's h (coalesced)
        if (t && tid < 128) {
            const __half* Ac = A + cur * 16 * AS1;
            uint2 v = *(const uint2*)(Ac + ffs * AS1 + ffc * 4);
            *(uint2*)(fout + (size_t)(t0 + (t - 1) * step) * 128) = v;
        }

        if (xf) {
            An[fsx * AS1 + 64 + comp] = hi_h(vn);
            An[fsx * AS1 + 68 + comp] = lo_h(vn);
            vn = vi;
            vi = (t + 3 < TT) ? __ldg(xp + (size_t)(t + 3) * step * 4) : 0.f;
        }

        // epilogue: one cell per lane
        {
            float iv = sig_h (aA0[0] + aB0[0] + bi);
            float fv = sig_h (aA0[1] + aB0[1] + bff);
            float gv = tanh_f(aA1[0] + aB1[0] + bg);
            float ov = sig_h (aA1[1] + aB1[1] + bo);
            c = fv * c + iv * gv;
            float h = ov * tanh_f(c);
            An[srow * AS1 + j] = hi_h(h);
        }
        __syncthreads();
    }

    if (tid < 128) {
        uint2 v = *(const uint2*)(A + ffs * AS1 + ffc * 4);
        *(uint2*)(fout + (size_t)(t0 + (TT - 1) * step) * 128) = v;
    }
}

// =====================================================================
// pre2 GEMM: g_pre2p[m, n2] = sum_k out1h[m,k] * B2i[n2,k] + bias (scaled)
// =====================================================================
#define ASG 136
__global__ __launch_bounds__(256, 2)
void pre2_gemm(const float* __restrict__ b2)
{
    const int m0 = blockIdx.x * 128;
    const int tid = threadIdx.x, lane = tid & 31, w = tid >> 5;

    __shared__ __half As[128 * ASG];

    {
        const uint4* src = (const uint4*)(g_out1h + (size_t)m0 * 128);
        for (int i = tid; i < 128 * 16; i += 256) {
            int rr = i >> 4, cc = i & 15;
            *(uint4*)&As[rr * ASG + cc * 8] = __ldg(src + i);
        }
    }
    __syncthreads();

    const uint32_t aaddr = smem_u32(As) + (((w * 16) + (lane & 15)) * ASG + (lane >> 4) * 8) * 2;

    float* outp = g_pre2p + (size_t)(m0 + w * 16) * 256;
    const int row0 = lane >> 2;

#pragma unroll 1
    for (int ng = 0; ng < 8; ng++) {
        uint32_t bfr[4][8][2];
#pragma unroll
        for (int tt = 0; tt < 4; tt++) {
            const int n = ng * 32 + tt * 8 + (lane >> 2);
#pragma unroll
            for (int kt = 0; kt < 8; kt++) {
                const __half* p = g_B2i + (size_t)n * 128 + kt * 16 + 2 * (lane & 3);
                bfr[tt][kt][0] = *(const uint32_t*)p;
                bfr[tt][kt][1] = *(const uint32_t*)(p + 8);
            }
        }

        float acc[4][4];
#pragma unroll
        for (int i = 0; i < 4; i++) { acc[i][0] = 0.f; acc[i][1] = 0.f; acc[i][2] = 0.f; acc[i][3] = 0.f; }
#pragma unroll
        for (int kt = 0; kt < 8; kt++) {
            uint32_t a[4];
            ldsm4(a, aaddr + kt * 32);
            mma16816(acc[0], a, bfr[0][kt]);
            mma16816(acc[1], a, bfr[1][kt]);
            mma16816(acc[2], a, bfr[2][kt]);
            mma16816(acc[3], a, bfr[3][kt]);
        }

#pragma unroll
        for (int tt = 0; tt < 4; tt++) {
            const int col = ng * 32 + tt * 8 + 2 * (lane & 3);
            const int ra = (col & 3) * 64 + (col >> 2);
            const int rb = ((col + 1) & 3) * 64 + ((col + 1) >> 2);
            const float sa = ((col & 3) == 2) ? 1.f : 0.5f;
            const float ba = __ldg(b2 + ra) * sa;
            const float bb = __ldg(b2 + rb) * 0.5f;
            float2 v0 = make_float2(acc[tt][0] + ba, acc[tt][1] + bb);
            float2 v1 = make_float2(acc[tt][2] + ba, acc[tt][3] + bb);
            *(float2*)(outp + (size_t)row0 * 256 + col)       = v0;
            *(float2*)(outp + (size_t)(row0 + 8) * 256 + col) = v1;
        }
    }
}

// =====================================================================
// Layer-2 scan: 8 samples/block, 32 blocks, 512 threads. K=64, 4 kt.
// Warp w owns tiles {2w, 2w+1} -> 1 cell/lane; pre2 quad = 1 float4/lane.
// =====================================================================
#define AS2 72
__global__ __launch_bounds__(512, 1)
void l2_scan(const float* __restrict__ Wfc, const float* __restrict__ bfc,
             float* __restrict__ out)
{
    const int s0  = blockIdx.x * 8;
    const int tid = threadIdx.x, lane = tid & 31, w = tid >> 5;

    __shared__ __half A[2 * 16 * AS2];
    __shared__ float  sred[8 * 64];

    for (int i = tid; i < 2 * 16 * AS2; i += 512) A[i] = __ushort_as_half(0);

    uint32_t bf[2][4][2];
#pragma unroll
    for (int tt = 0; tt < 2; tt++) {
        const int n = (2 * w + tt) * 8 + (lane >> 2);
#pragma unroll
        for (int kt = 0; kt < 4; kt++) {
            const __half* p = g_B2s + (size_t)n * 64 + kt * 16 + 2 * (lane & 3);
            bf[tt][kt][0] = *(const uint32_t*)p;
            bf[tt][kt][1] = *(const uint32_t*)(p + 8);
        }
    }

    const int srow = lane >> 2;
    const int j    = (w >> 1) * 8 + 2 * (lane & 3) + (w & 1);
    const float wf = __ldg(Wfc + j);

    const uint32_t lrow = lane & 15, lcol = (lane >> 4) * 8;
    const uint32_t aaddr0 = smem_u32(A) + (lrow * AS2 + lcol) * 2;
    const uint32_t aaddr1 = aaddr0 + 16 * AS2 * 2;

    // pre2 stream: one (i,f,g,o) quad per lane, depth-3 prefetch
    const float* pp = g_pre2p + (size_t)(s0 + srow) * TT * 256 + j * 4;
    float4 pc = *(const float4*)(pp);
    float4 pn = *(const float4*)(pp + 256);
    float4 pi = *(const float4*)(pp + 512);
    __syncthreads();

    float c = 0.f, h = 0.f;

    for (int t = 0; t < TT; t++) {
        const int cur = t & 1, nxt = cur ^ 1;
        const uint32_t aaddr = cur ? aaddr1 : aaddr0;
        __half* An = A + nxt * 16 * AS2;

        float aA0[4], aB0[4], aA1[4], aB1[4];
#pragma unroll
        for (int q = 0; q < 4; q++) { aA0[q] = 0.f; aB0[q] = 0.f; aA1[q] = 0.f; aB1[q] = 0.f; }
#pragma unroll
        for (int kt = 0; kt < 4; kt++) {
            uint32_t a[4];
            ldsm4(a, aaddr + kt * 32);
            if (kt < 2) { mma16816(aA0, a, bf[0][kt]); mma16816(aA1, a, bf[1][kt]); }
            else        { mma16816(aB0, a, bf[0][kt]); mma16816(aB1, a, bf[1][kt]); }
        }

        float4 pf;
        if (t + 3 < TT) pf = *(const float4*)(pp + (size_t)(t + 3) * 256);
        else            pf = make_float4(0.f, 0.f, 0.f, 0.f);

        {
            float iv = sig_h (aA0[0] + aB0[0] + pc.x);
            float fv = sig_h (aA0[1] + aB0[1] + pc.y);
            float gv = tanh_f(aA1[0] + aB1[0] + pc.z);
            float ov = sig_h (aA1[1] + aB1[1] + pc.w);
            c = fv * c + iv * gv;
            h = ov * tanh_f(c);
            An[srow * AS2 + j] = hi_h(h);
        }

        pc = pn; pn = pi; pi = pf;
        __syncthreads();
    }

    // fused FC on final h
    sred[srow * 64 + j] = h * wf;
    __syncthreads();
    if (tid < 8) {
        float acc = __ldg(bfc);
#pragma unroll
        for (int k = 0; k < 64; k++) acc += sred[tid * 64 + k];
        out[s0 + tid] = acc;
    }
}

// =====================================================================
extern "C" void kernel_launch(void* const* d_in, const int* in_sizes, int n_in,
                              void* d_out, int out_size)
{
    const float* x     = (const float*)d_in[0];
    const float* Wih_f = (const float*)d_in[1];
    const float* Whh_f = (const float*)d_in[2];
    const float* b_f   = (const float*)d_in[3];
    const float* Wih_b = (const float*)d_in[4];
    const float* Whh_b = (const float*)d_in[5];
    const float* b_b   = (const float*)d_in[6];
    const float* Wih2  = (const float*)d_in[7];
    const float* Whh2  = (const float*)d_in[8];
    const float* b2    = (const float*)d_in[9];
    const float* Wfc   = (const float*)d_in[10];
    const float* bfc   = (const float*)d_in[11];
    float* out = (float*)d_out;

    build_B<<<256, 256>>>(Wih_f, Whh_f, Wih_b, Whh_b, Wih2, Whh2);
    l1_scan<<<64, 512>>>(x, b_f, b_b);
    pre2_gemm<<<(BB * TT) / 128, 256>>>(b2);
    l2_scan<<<32, 512>>>(Wfc, bfc, out);
}